// round 11
// baseline (speedup 1.0000x reference)
#include <cuda_runtime.h>
#include <cuda_bf16.h>
#include <math.h>
#include <stdint.h>

// Problem dims
#define BATCH 64
#define PP    196
#define TT    30
#define VV    30000
#define NPAD  30080
#define KEXT  1536      // 3 x 512 (hi*hi + hi*lo + lo*hi)

// ---------------- device scratch ----------------
__device__ float g_enc_proj[BATCH * PP * 512];
__device__ float g_h[BATCH * 512];
__device__ float g_c[BATCH * 512];
__device__ float g_hgate[BATCH * 1024];          // [dec_proj(+bias) | gate_raw(+bias)]
__device__ float g_scores[BATCH * PP];
__device__ float g_x[BATCH * 1536];
__device__ float g_gates[BATCH * 2048];
__device__ float g_Wcat[1536 * 2048];
__device__ float g_bias4[2048];
__device__ float g_Wdb[512 * 1024];              // [Wd | W_beta] k-major
__device__ float g_biasdb[1024];
__device__ float g_gpre[1920 * 2048];            // precomputed emb@W_ih + bias
__device__ float g_H[TT * BATCH * 512];

__device__ __nv_bfloat16 g_Aext[12544 * KEXT];   // feats ext; reused for H ext
__device__ __nv_bfloat16 g_Bext[NPAD * KEXT];    // W_fc^T ext
__device__ __nv_bfloat16 g_Wext[512 * KEXT];     // We_att^T ext
__device__ __nv_bfloat16 g_Wihext[2048 * KEXT];  // W_ih[0:512]^T ext
__device__ __nv_bfloat16 g_Eext[1920 * KEXT];    // gathered emb ext

__device__ __forceinline__ float sigf(float x) { return 1.f / (1.f + expf(-x)); }
__device__ __forceinline__ float tanh_a(float x) {
    float y; asm("tanh.approx.f32 %0, %1;" : "=f"(y) : "f"(x)); return y;
}
__device__ __forceinline__ uint32_t smem_u32(const void* p) {
    uint32_t a;
    asm("{ .reg .u64 t; cvta.to.shared.u64 t, %1; cvt.u32.u64 %0, t; }" : "=r"(a) : "l"(p));
    return a;
}

// ---------------- mma.sync bf16 GEMM ----------------
#define NSTAGE (KEXT / 64)   // 24

__device__ __forceinline__ void ldm4(uint32_t* r, uint32_t addr) {
    asm volatile("ldmatrix.sync.aligned.m8n8.x4.shared.b16 {%0,%1,%2,%3}, [%4];"
        : "=r"(r[0]), "=r"(r[1]), "=r"(r[2]), "=r"(r[3]) : "r"(addr));
}
__device__ __forceinline__ void mma16816(float* c, const uint32_t* a, uint32_t b0, uint32_t b1) {
    asm volatile("mma.sync.aligned.m16n8k16.row.col.f32.bf16.bf16.f32 "
        "{%0,%1,%2,%3}, {%4,%5,%6,%7}, {%8,%9}, {%0,%1,%2,%3};"
        : "+f"(c[0]), "+f"(c[1]), "+f"(c[2]), "+f"(c[3])
        : "r"(a[0]), "r"(a[1]), "r"(a[2]), "r"(a[3]), "r"(b0), "r"(b1));
}
#define CPA(saddr, gaddr) \
    asm volatile("cp.async.cg.shared.global [%0], [%1], 16;" :: "r"(saddr), "l"(gaddr))
#define CPA_COMMIT() asm volatile("cp.async.commit_group;")
#define CPA_WAIT0()  asm volatile("cp.async.wait_group 0;")

template <int EPI>
__global__ void __launch_bounds__(256) mma_gemm(
    const __nv_bfloat16* __restrict__ Aext, const __nv_bfloat16* __restrict__ Bext,
    float* __restrict__ C, const float* __restrict__ bias,
    int Nld, int Mreal, int Nreal)
{
    extern __shared__ char sm[];
    const uint32_t sb = smem_u32(sm);
    const int tid = threadIdx.x;
    const int m0 = (EPI == 2 ? blockIdx.x : blockIdx.y) * 128;
    const int n0 = (EPI == 2 ? blockIdx.y : blockIdx.x) * 128;

    const __nv_bfloat16* Ag = Aext + (long)m0 * KEXT;
    const __nv_bfloat16* Bg = Bext + (long)n0 * KEXT;

    const int wid = tid >> 5, lane = tid & 31;
    const int wm = wid & 3, wn = wid >> 2;
    const int g = lane >> 3, r = lane & 7;
    const int lrow = (g & 1) * 8 + r;
    const uint32_t lkb = (g >> 1) * 16;
    const uint32_t xorp = (uint32_t)(r << 4);

    uint32_t aoff[2], boff[4];
#pragma unroll
    for (int mt = 0; mt < 2; mt++) aoff[mt] = (uint32_t)((wm * 32 + mt * 16 + lrow) * 128);
#pragma unroll
    for (int bt = 0; bt < 4; bt++) boff[bt] = (uint32_t)(16384 + (wn * 64 + bt * 16 + lrow) * 128);

    float acc[2][8][4];
#pragma unroll
    for (int i = 0; i < 2; i++)
#pragma unroll
        for (int j = 0; j < 8; j++)
#pragma unroll
            for (int q = 0; q < 4; q++) acc[i][j][q] = 0.f;

    {
#pragma unroll
        for (int i = 0; i < 4; i++) {
            int idx = i * 256 + tid;
            int row = idx >> 3, c = idx & 7;
            uint32_t so = (uint32_t)(row * 128 + ((c * 16) ^ ((row & 7) << 4)));
            CPA(sb + so, Ag + (long)row * KEXT + c * 8);
            CPA(sb + 16384 + so, Bg + (long)row * KEXT + c * 8);
        }
        CPA_COMMIT();
    }

    for (int s = 0; s < NSTAGE; s++) {
        CPA_WAIT0();
        __syncthreads();
        if (s + 1 < NSTAGE) {
            const uint32_t dstb = sb + ((s + 1) & 1) * 32768;
            const long kb = (long)(s + 1) * 64;
#pragma unroll
            for (int i = 0; i < 4; i++) {
                int idx = i * 256 + tid;
                int row = idx >> 3, c = idx & 7;
                uint32_t so = (uint32_t)(row * 128 + ((c * 16) ^ ((row & 7) << 4)));
                CPA(dstb + so, Ag + (long)row * KEXT + kb + c * 8);
                CPA(dstb + 16384 + so, Bg + (long)row * KEXT + kb + c * 8);
            }
            CPA_COMMIT();
        }

        const uint32_t sbase = sb + (s & 1) * 32768;
#pragma unroll
        for (int kk = 0; kk < 4; kk++) {
            const uint32_t kb = (uint32_t)(kk * 32 + lkb) ^ xorp;
            uint32_t a0[4], a1[4];
            ldm4(a0, sbase + aoff[0] + kb);
            ldm4(a1, sbase + aoff[1] + kb);
#pragma unroll
            for (int bt = 0; bt < 4; bt++) {
                uint32_t bm[4];
                ldm4(bm, sbase + boff[bt] + kb);
                mma16816(acc[0][2 * bt],     a0, bm[0], bm[2]);
                mma16816(acc[1][2 * bt],     a1, bm[0], bm[2]);
                mma16816(acc[0][2 * bt + 1], a0, bm[1], bm[3]);
                mma16816(acc[1][2 * bt + 1], a1, bm[1], bm[3]);
            }
        }
        __syncthreads();
    }

    // epilogue
    const int crow0 = lane >> 2;
    const int ccol = (lane & 3) * 2;
#pragma unroll
    for (int mt = 0; mt < 2; mt++) {
#pragma unroll
        for (int h = 0; h < 2; h++) {
            const int m = m0 + wm * 32 + mt * 16 + crow0 + h * 8;
            if (EPI == 2) {
                if (m < Mreal) {
                    int t = (m >> 6) + 1;
                    int b = m & 63;
                    float* crow = C + (long)b * (TT * VV) + (long)t * VV;
#pragma unroll
                    for (int nt = 0; nt < 8; nt++) {
                        const int n = n0 + wn * 64 + nt * 8 + ccol;
                        if (n < Nreal) {
                            float2 o;
                            o.x = acc[mt][nt][h * 2 + 0] + bias[n];
                            o.y = acc[mt][nt][h * 2 + 1] + bias[n + 1];
                            *reinterpret_cast<float2*>(crow + n) = o;
                        }
                    }
                }
            } else {
                float* crow = C + (long)m * Nld;
#pragma unroll
                for (int nt = 0; nt < 8; nt++) {
                    const int n = n0 + wn * 64 + nt * 8 + ccol;
                    float2 o;
                    o.x = acc[mt][nt][h * 2 + 0] + bias[n];
                    o.y = acc[mt][nt][h * 2 + 1] + bias[n + 1];
                    *reinterpret_cast<float2*>(crow + n) = o;
                }
            }
        }
    }
}

// ---------------- conversion kernels ----------------
__global__ void k_cvt_ext(const float* __restrict__ src, __nv_bfloat16* __restrict__ dst, int n) {
    int i = blockIdx.x * 256 + threadIdx.x;
    if (i < n) {
        int row = i >> 9, k = i & 511;
        float x = src[i];
        __nv_bfloat16 h = __float2bfloat16(x);
        __nv_bfloat16 l = __float2bfloat16(x - __bfloat162float(h));
        __nv_bfloat16* d = dst + (long)row * KEXT + k;
        d[0] = h; d[512] = h; d[1024] = l;
    }
}

__global__ void k_gather_emb(const int* __restrict__ captions, const float* __restrict__ emb) {
    int i = blockIdx.x * 256 + threadIdx.x;
    if (i < 1856 * 512) {
        int rrow = i >> 9, d = i & 511;
        int t = rrow >> 6, b = rrow & 63;
        int tok = captions[b * TT + t];
        float x = emb[(long)tok * 512 + d];
        __nv_bfloat16 h = __float2bfloat16(x);
        __nv_bfloat16 l = __float2bfloat16(x - __bfloat162float(h));
        __nv_bfloat16* dd = g_Eext + (long)rrow * KEXT + d;
        dd[0] = h; dd[512] = h; dd[1024] = l;
    }
}

__global__ void k_tsp_ext(const float* __restrict__ src, __nv_bfloat16* __restrict__ dst,
                          int N, int Npad) {
    __shared__ float t[32][33];
    int n0 = blockIdx.x * 32, k0 = blockIdx.y * 32;
    int tx = threadIdx.x, ty = threadIdx.y;
#pragma unroll
    for (int i = 0; i < 32; i += 8) {
        int k = k0 + ty + i, n = n0 + tx;
        t[ty + i][tx] = (n < N) ? src[(long)k * N + n] : 0.f;
    }
    __syncthreads();
#pragma unroll
    for (int i = 0; i < 32; i += 8) {
        int n = n0 + ty + i, k = k0 + tx;
        if (n < Npad) {
            float x = t[tx][ty + i];
            __nv_bfloat16 h = __float2bfloat16(x);
            __nv_bfloat16 l = __float2bfloat16(x - __bfloat162float(h));
            __nv_bfloat16* d = dst + (long)n * KEXT + k;
            d[0] = h; d[512] = l; d[1024] = h;
        }
    }
}

// ---------------- packed f32x2 SIMT GEMM (split-K atomic) ----------------
__device__ __forceinline__ unsigned long long pack2(float x) {
    unsigned long long r;
    asm("mov.b64 %0, {%1, %1};" : "=l"(r) : "f"(x));
    return r;
}
__device__ __forceinline__ void fma2(unsigned long long& d, unsigned long long a, unsigned long long b) {
    asm("fma.rn.f32x2 %0, %1, %2, %0;" : "+l"(d) : "l"(a), "l"(b));
}
__device__ __forceinline__ float2 unpack2(unsigned long long v) {
    float2 r;
    asm("mov.b64 {%0, %1}, %2;" : "=f"(r.x), "=f"(r.y) : "l"(v));
    return r;
}

__global__ void __launch_bounds__(256) gemm_gates(
    const float* __restrict__ A, const float* __restrict__ B,
    float* __restrict__ C, int N, int lda, int kLen)
{
    __shared__ float As[2][16][64];
    __shared__ float Bs[2][16][128];

    const int tid = threadIdx.x;
    const int n0 = blockIdx.x * 128;
    const int kStart = blockIdx.z * kLen;
    const int tn = (tid & 15) * 8;
    const int tm = (tid >> 4) * 4;
    const int am = tid >> 2, ak = (tid & 3) * 4;
    const int bk = tid >> 4, bn = (tid & 15) * 8;

    const float* Aptr = A + (long)am * lda + kStart + ak;
    const float* Bptr = B + (long)(kStart + bk) * N + n0 + bn;

    unsigned long long acc[4][4];
#pragma unroll
    for (int i = 0; i < 4; i++) acc[i][0] = acc[i][1] = acc[i][2] = acc[i][3] = 0ull;

    const int nb = kLen / 16;
    float4 ar0, br0, br1;
    ar0 = *reinterpret_cast<const float4*>(Aptr);
    br0 = *reinterpret_cast<const float4*>(Bptr);
    br1 = *reinterpret_cast<const float4*>(Bptr + 4);
    As[0][ak + 0][am] = ar0.x; As[0][ak + 1][am] = ar0.y;
    As[0][ak + 2][am] = ar0.z; As[0][ak + 3][am] = ar0.w;
    *reinterpret_cast<float4*>(&Bs[0][bk][bn]) = br0;
    *reinterpret_cast<float4*>(&Bs[0][bk][bn + 4]) = br1;
    __syncthreads();

    for (int ib = 0; ib < nb; ib++) {
        const int cur = ib & 1;
        const bool more = (ib + 1) < nb;
        if (more) {
            ar0 = *reinterpret_cast<const float4*>(Aptr + (ib + 1) * 16);
            const float* bp = Bptr + (long)((ib + 1) * 16) * N;
            br0 = *reinterpret_cast<const float4*>(bp);
            br1 = *reinterpret_cast<const float4*>(bp + 4);
        }
#pragma unroll
        for (int kk = 0; kk < 16; kk++) {
            unsigned long long ad[4];
            float4 af = *reinterpret_cast<const float4*>(&As[cur][kk][tm]);
            ad[0] = pack2(af.x); ad[1] = pack2(af.y); ad[2] = pack2(af.z); ad[3] = pack2(af.w);
            ulonglong2 bv0 = *reinterpret_cast<const ulonglong2*>(&Bs[cur][kk][tn]);
            ulonglong2 bv1 = *reinterpret_cast<const ulonglong2*>(&Bs[cur][kk][tn + 4]);
#pragma unroll
            for (int i = 0; i < 4; i++) {
                fma2(acc[i][0], ad[i], bv0.x);
                fma2(acc[i][1], ad[i], bv0.y);
                fma2(acc[i][2], ad[i], bv1.x);
                fma2(acc[i][3], ad[i], bv1.y);
            }
        }
        if (more) {
            const int nxt = cur ^ 1;
            As[nxt][ak + 0][am] = ar0.x; As[nxt][ak + 1][am] = ar0.y;
            As[nxt][ak + 2][am] = ar0.z; As[nxt][ak + 3][am] = ar0.w;
            *reinterpret_cast<float4*>(&Bs[nxt][bk][bn]) = br0;
            *reinterpret_cast<float4*>(&Bs[nxt][bk][bn + 4]) = br1;
        }
        __syncthreads();
    }

#pragma unroll
    for (int i = 0; i < 4; i++) {
        float* crow = C + (long)(tm + i) * N;
        float2 v[4];
        v[0] = unpack2(acc[i][0]); v[1] = unpack2(acc[i][1]);
        v[2] = unpack2(acc[i][2]); v[3] = unpack2(acc[i][3]);
#pragma unroll
        for (int j = 0; j < 4; j++) {
            int gn = n0 + tn + 2 * j;
            atomicAdd(crow + gn, v[j].x);
            atomicAdd(crow + gn + 1, v[j].y);
        }
    }
}

// ---------------- small kernels ----------------
__global__ void k_zero_t0(float* __restrict__ out) {
    int idx = blockIdx.x * 256 + threadIdx.x;
    if (idx < BATCH * VV) {
        int b = idx / VV, v = idx - b * VV;
        out[(long)b * (TT * VV) + v] = 0.f;
    }
}

__global__ void k_init_hc(const float* __restrict__ pooled,
                          const float* __restrict__ Wh, const float* __restrict__ bh,
                          const float* __restrict__ Wc, const float* __restrict__ bc) {
    int b = blockIdx.y;
    int j = blockIdx.x * 256 + threadIdx.x;
    __shared__ float pr[512];
    pr[threadIdx.x] = pooled[b * 512 + threadIdx.x];
    pr[threadIdx.x + 256] = pooled[b * 512 + threadIdx.x + 256];
    __syncthreads();
    float a0 = 0, a1 = 0, a2 = 0, a3 = 0;
    const float* W = (j < 512) ? (Wh + j) : (Wc + j - 512);
    for (int k = 0; k < 512; k += 4) {
        a0 += pr[k] * W[k * 512];
        a1 += pr[k + 1] * W[(k + 1) * 512];
        a2 += pr[k + 2] * W[(k + 2) * 512];
        a3 += pr[k + 3] * W[(k + 3) * 512];
    }
    float s = (a0 + a1) + (a2 + a3);
    if (j < 512) g_h[b * 512 + j] = tanhf(s + bh[j]);
    else         g_c[b * 512 + (j - 512)] = tanhf(s + bc[j - 512]);
}

__global__ void k_wcat(const float* __restrict__ Wih, const float* __restrict__ Whh,
                       const float* __restrict__ bih, const float* __restrict__ bhh) {
    int idx = blockIdx.x * 256 + threadIdx.x;
    if (idx < 1536 * 2048) {
        int k = idx >> 11, n = idx & 2047;
        g_Wcat[idx] = (k < 1024) ? Wih[idx] : Whh[(k - 1024) * 2048 + n];
    }
    if (idx < 2048) g_bias4[idx] = bih[idx] + bhh[idx];
}

// build [Wd | W_beta] k-major + biasdb
__global__ void k_wdb(const float* __restrict__ Wd, const float* __restrict__ Wb,
                      const float* __restrict__ bd, const float* __restrict__ bb) {
    int idx = blockIdx.x * 256 + threadIdx.x;
    if (idx < 512 * 1024) {
        int k = idx >> 10, j = idx & 1023;
        g_Wdb[idx] = (j < 512) ? Wd[k * 512 + j] : Wb[k * 512 + (j - 512)];
    }
    if (idx < 1024) g_biasdb[idx] = (idx < 512) ? bd[idx] : bb[idx - 512];
}

// prologue: hgate=bias, x h-slot, gates=gpre row 0
__global__ void k_prep0() {
    int idx = blockIdx.x * 256 + threadIdx.x;   // 32768
    int b = idx >> 9, d = idx & 511;
    g_x[b * 1536 + 1024 + d] = g_h[idx];
    g_hgate[b * 1024 + d] = g_biasdb[d];
    g_hgate[b * 1024 + 512 + d] = g_biasdb[512 + d];
    float* gg = g_gates + b * 2048;
    const float* gp = g_gpre + b * 2048;
    gg[d]        = gp[d];
    gg[512 + d]  = gp[512 + d];
    gg[1024 + d] = gp[1024 + d];
    gg[1536 + d] = gp[1536 + d];
}

__global__ void k_att(const float* __restrict__ wf, const float* __restrict__ bf) {
    int b = blockIdx.x / 25;
    int pc = blockIdx.x % 25;
    __shared__ float dp[512], wfs[512];
    dp[threadIdx.x] = g_hgate[b * 1024 + threadIdx.x];
    dp[threadIdx.x + 256] = g_hgate[b * 1024 + threadIdx.x + 256];
    wfs[threadIdx.x] = wf[threadIdx.x];
    wfs[threadIdx.x + 256] = wf[threadIdx.x + 256];
    __syncthreads();
    int p = pc * 8 + (threadIdx.x >> 5);
    int lane = threadIdx.x & 31;
    if (p < PP) {
        const float* ep = g_enc_proj + ((long)(b * PP + p)) * 512;
        float acc = 0.f;
#pragma unroll
        for (int i = 0; i < 16; i++) {
            int a = i * 32 + lane;
            acc += tanh_a(ep[a] + dp[a]) * wfs[a];
        }
#pragma unroll
        for (int off = 16; off; off >>= 1) acc += __shfl_down_sync(0xffffffffu, acc, off);
        if (lane == 0) g_scores[b * PP + p] = acc + bf[0];
    }
}

__global__ void k_softmax_ctx(const float* __restrict__ feats) {
    int b = blockIdx.x;
    int tid = threadIdx.x;
    __shared__ float sc[256];
    __shared__ float red[256];
    float v = (tid < PP) ? g_scores[b * PP + tid] : -1e30f;
    red[tid] = v;
    __syncthreads();
    for (int s = 128; s > 0; s >>= 1) {
        if (tid < s) red[tid] = fmaxf(red[tid], red[tid + s]);
        __syncthreads();
    }
    float mx = red[0];
    __syncthreads();
    float e = (tid < PP) ? expf(v - mx) : 0.f;
    red[tid] = e;
    __syncthreads();
    for (int s = 128; s > 0; s >>= 1) {
        if (tid < s) red[tid] += red[tid + s];
        __syncthreads();
    }
    sc[tid] = e / red[0];
    __syncthreads();

    int d = blockIdx.y * 256 + tid;
    const float* fp = feats + (long)b * PP * 512 + d;
    float acc = 0.f;
#pragma unroll 4
    for (int p = 0; p < PP; p++) acc += sc[p] * fp[p * 512];
    g_x[b * 1536 + 512 + d] = acc * sigf(g_hgate[b * 1024 + 512 + d]);
}

// LSTM + next-step prep (hgate bias re-init, gates<-gpre, h->x)
__global__ void k_lstm(int tm1) {
    int idx = blockIdx.x * 256 + threadIdx.x;
    int b = idx >> 9, d = idx & 511;
    float* gg = g_gates + b * 2048;
    float ig = sigf(gg[d]);
    float fg = sigf(gg[512 + d]);
    float gv = tanhf(gg[1024 + d]);
    float og = sigf(gg[1536 + d]);
    float c2 = fg * g_c[idx] + ig * gv;
    float h2 = og * tanhf(c2);
    g_c[idx] = c2;
    g_h[idx] = h2;
    g_H[((long)tm1 * BATCH + b) * 512 + d] = h2;
    g_x[b * 1536 + 1024 + d] = h2;
    g_hgate[b * 1024 + d] = g_biasdb[d];
    g_hgate[b * 1024 + 512 + d] = g_biasdb[512 + d];
    if (tm1 < TT - 2) {
        const float* gp = g_gpre + (long)(tm1 + 1) * 131072 + b * 2048;
        gg[d]        = gp[d];
        gg[512 + d]  = gp[512 + d];
        gg[1024 + d] = gp[1024 + d];
        gg[1536 + d] = gp[1536 + d];
    }
}

// ---------------- launcher ----------------
extern "C" void kernel_launch(void* const* d_in, const int* in_sizes, int n_in,
                              void* d_out, int out_size) {
    const float* encoder_feats  = (const float*)d_in[0];
    const float* encoder_pooled = (const float*)d_in[1];
    const int*   captions       = (const int*)d_in[2];
    const float* We_att  = (const float*)d_in[3];
    const float* be_att  = (const float*)d_in[4];
    const float* Wd_att  = (const float*)d_in[5];
    const float* bd_att  = (const float*)d_in[6];
    const float* wf_att  = (const float*)d_in[7];
    const float* bf_att  = (const float*)d_in[8];
    const float* emb_table = (const float*)d_in[9];
    const float* W_ih = (const float*)d_in[10];
    const float* W_hh = (const float*)d_in[11];
    const float* b_ih = (const float*)d_in[12];
    const float* b_hh = (const float*)d_in[13];
    const float* W_init_h = (const float*)d_in[14];
    const float* b_init_h = (const float*)d_in[15];
    const float* W_init_c = (const float*)d_in[16];
    const float* b_init_c = (const float*)d_in[17];
    const float* W_fc  = (const float*)d_in[18];
    const float* b_fc  = (const float*)d_in[19];
    const float* W_beta = (const float*)d_in[20];
    const float* b_beta = (const float*)d_in[21];
    float* out = (float*)d_out;

    void* p;
    cudaGetSymbolAddress(&p, g_enc_proj); float* enc_proj_ptr = (float*)p;
    cudaGetSymbolAddress(&p, g_h);        float* h_ptr = (float*)p;
    cudaGetSymbolAddress(&p, g_hgate);    float* hgate_ptr = (float*)p;
    cudaGetSymbolAddress(&p, g_x);        float* x_ptr = (float*)p;
    cudaGetSymbolAddress(&p, g_Wcat);     float* wcat_ptr = (float*)p;
    cudaGetSymbolAddress(&p, g_Wdb);      float* wdb_ptr = (float*)p;
    cudaGetSymbolAddress(&p, g_gates);    float* gates_ptr = (float*)p;
    cudaGetSymbolAddress(&p, g_bias4);    float* bias4_ptr = (float*)p;
    cudaGetSymbolAddress(&p, g_gpre);     float* gpre_ptr = (float*)p;
    cudaGetSymbolAddress(&p, g_H);        float* H_ptr = (float*)p;
    cudaGetSymbolAddress(&p, g_Aext);     __nv_bfloat16* Aext = (__nv_bfloat16*)p;
    cudaGetSymbolAddress(&p, g_Bext);     __nv_bfloat16* Bext = (__nv_bfloat16*)p;
    cudaGetSymbolAddress(&p, g_Wext);     __nv_bfloat16* Wext = (__nv_bfloat16*)p;
    cudaGetSymbolAddress(&p, g_Wihext);   __nv_bfloat16* Wihext = (__nv_bfloat16*)p;
    cudaGetSymbolAddress(&p, g_Eext);     __nv_bfloat16* Eext = (__nv_bfloat16*)p;

    const int SMEM = 64 * 1024;
    cudaFuncSetAttribute(mma_gemm<0>, cudaFuncAttributeMaxDynamicSharedMemorySize, SMEM);
    cudaFuncSetAttribute(mma_gemm<1>, cudaFuncAttributeMaxDynamicSharedMemorySize, SMEM);
    cudaFuncSetAttribute(mma_gemm<2>, cudaFuncAttributeMaxDynamicSharedMemorySize, SMEM);

    // prologue
    k_zero_t0<<<(BATCH * VV + 255) / 256, 256>>>(out);
    k_init_hc<<<dim3(4, BATCH), 256>>>(encoder_pooled, W_init_h, b_init_h, W_init_c, b_init_c);
    k_wcat<<<(1536 * 2048 + 255) / 256, 256>>>(W_ih, W_hh, b_ih, b_hh);
    k_wdb<<<(512 * 1024 + 255) / 256, 256>>>(Wd_att, W_beta, bd_att, b_beta);
    k_tsp_ext<<<dim3(940, 16), dim3(32, 8)>>>(W_fc, Bext, VV, NPAD);
    k_tsp_ext<<<dim3(16, 16), dim3(32, 8)>>>(We_att, Wext, 512, 512);
    k_tsp_ext<<<dim3(64, 16), dim3(32, 8)>>>(W_ih, Wihext, 2048, 2048);
    k_cvt_ext<<<(12544 * 512 + 255) / 256, 256>>>(encoder_feats, Aext, 12544 * 512);
    k_gather_emb<<<(1856 * 512 + 255) / 256, 256>>>(captions, emb_table);
    mma_gemm<0><<<dim3(4, 98), 256, SMEM>>>(Aext, Wext, enc_proj_ptr, be_att, 512, 12544, 512);
    mma_gemm<1><<<dim3(16, 15), 256, SMEM>>>(Eext, Wihext, gpre_ptr, bias4_ptr, 2048, 1920, 2048);
    k_prep0<<<128, 256>>>();

    // recurrence: 5 launches per step
    for (int t = 1; t < TT; t++) {
        int tm1 = t - 1;
        // dec_proj/gate: hgate += h @ [Wd|Wb]  (64 x 1024, K=512, split-K 4)
        gemm_gates<<<dim3(8, 1, 4), 256>>>(h_ptr, wdb_ptr, hgate_ptr, 1024, 512, 128);
        k_att<<<64 * 25, 256>>>(wf_att, bf_att);
        k_softmax_ctx<<<dim3(BATCH, 2), 256>>>(encoder_feats);
        gemm_gates<<<dim3(16, 1, 8), 256>>>(x_ptr + 512, wcat_ptr + 512 * 2048, gates_ptr,
                                            2048, 1536, 128);
        k_lstm<<<128, 256>>>(tm1);
    }

    // vocab projection (m varies fastest: B L2-resident)
    k_cvt_ext<<<(1920 * 512 + 255) / 256, 256>>>(H_ptr, Aext, 1920 * 512);
    mma_gemm<2><<<dim3(15, NPAD / 128), 256, SMEM>>>(Aext, Bext, out, b_fc,
                                                     VV, (TT - 1) * BATCH, VV);
}

// round 12
// speedup vs baseline: 1.0913x; 1.0913x over previous
#include <cuda_runtime.h>
#include <cuda_bf16.h>
#include <cuda_fp16.h>
#include <math.h>
#include <stdint.h>

// Problem dims
#define BATCH 64
#define PP    196
#define TT    30
#define VV    30000
#define NPAD  30080
#define KEXT  1536      // 3 x 512 (hi*hi + hi*lo + lo*hi)

// ---------------- device scratch ----------------
__device__ float g_h[BATCH * 512];
__device__ float g_c[BATCH * 512];
__device__ float g_hgate[BATCH * 1024];
__device__ float g_scores[BATCH * PP];
__device__ float g_x[BATCH * 1536];
__device__ float g_gates[BATCH * 2048];
__device__ float g_Wcat[1536 * 2048];
__device__ float g_bias4[2048];
__device__ float g_gpre[1920 * 2048];            // precomputed emb@W_ih + bias
__device__ float g_H[TT * BATCH * 512];

__device__ __half2 g_ep2[12544 * 256];           // enc_proj half2
__device__ __half2 g_feats2[12544 * 256];        // encoder_feats half2

__device__ __nv_bfloat16 g_Aext[12544 * KEXT];   // feats ext; reused for H ext
__device__ __nv_bfloat16 g_Bext[NPAD * KEXT];    // W_fc^T ext
__device__ __nv_bfloat16 g_Wext[512 * KEXT];     // We_att^T ext
__device__ __nv_bfloat16 g_Wihext[2048 * KEXT];  // W_ih[0:512]^T ext
__device__ __nv_bfloat16 g_Eext[1920 * KEXT];    // gathered emb ext

__device__ __forceinline__ float sigf(float x) { return 1.f / (1.f + expf(-x)); }
__device__ __forceinline__ float tanh_a(float x) {
    float y; asm("tanh.approx.f32 %0, %1;" : "=f"(y) : "f"(x)); return y;
}
__device__ __forceinline__ uint32_t smem_u32(const void* p) {
    uint32_t a;
    asm("{ .reg .u64 t; cvta.to.shared.u64 t, %1; cvt.u32.u64 %0, t; }" : "=r"(a) : "l"(p));
    return a;
}

// ---------------- mma.sync bf16 GEMM ----------------
#define NSTAGE (KEXT / 64)   // 24

__device__ __forceinline__ void ldm4(uint32_t* r, uint32_t addr) {
    asm volatile("ldmatrix.sync.aligned.m8n8.x4.shared.b16 {%0,%1,%2,%3}, [%4];"
        : "=r"(r[0]), "=r"(r[1]), "=r"(r[2]), "=r"(r[3]) : "r"(addr));
}
__device__ __forceinline__ void mma16816(float* c, const uint32_t* a, uint32_t b0, uint32_t b1) {
    asm volatile("mma.sync.aligned.m16n8k16.row.col.f32.bf16.bf16.f32 "
        "{%0,%1,%2,%3}, {%4,%5,%6,%7}, {%8,%9}, {%0,%1,%2,%3};"
        : "+f"(c[0]), "+f"(c[1]), "+f"(c[2]), "+f"(c[3])
        : "r"(a[0]), "r"(a[1]), "r"(a[2]), "r"(a[3]), "r"(b0), "r"(b1));
}
#define CPA(saddr, gaddr) \
    asm volatile("cp.async.cg.shared.global [%0], [%1], 16;" :: "r"(saddr), "l"(gaddr))
#define CPA_COMMIT() asm volatile("cp.async.commit_group;")
#define CPA_WAIT0()  asm volatile("cp.async.wait_group 0;")

// EPI 0: enc_proj -> g_ep2 (half2, +bias). EPI 1: fp32 C row-major + bias.
// EPI 2: vocab scatter + bias (m on blockIdx.x -> B stays L2-resident).
template <int EPI>
__global__ void __launch_bounds__(256) mma_gemm(
    const __nv_bfloat16* __restrict__ Aext, const __nv_bfloat16* __restrict__ Bext,
    float* __restrict__ C, const float* __restrict__ bias,
    int Nld, int Mreal, int Nreal)
{
    extern __shared__ char sm[];
    const uint32_t sb = smem_u32(sm);
    const int tid = threadIdx.x;
    const int m0 = (EPI == 2 ? blockIdx.x : blockIdx.y) * 128;
    const int n0 = (EPI == 2 ? blockIdx.y : blockIdx.x) * 128;

    const __nv_bfloat16* Ag = Aext + (long)m0 * KEXT;
    const __nv_bfloat16* Bg = Bext + (long)n0 * KEXT;

    const int wid = tid >> 5, lane = tid & 31;
    const int wm = wid & 3, wn = wid >> 2;
    const int g = lane >> 3, r = lane & 7;
    const int lrow = (g & 1) * 8 + r;
    const uint32_t lkb = (g >> 1) * 16;
    const uint32_t xorp = (uint32_t)(r << 4);

    uint32_t aoff[2], boff[4];
#pragma unroll
    for (int mt = 0; mt < 2; mt++) aoff[mt] = (uint32_t)((wm * 32 + mt * 16 + lrow) * 128);
#pragma unroll
    for (int bt = 0; bt < 4; bt++) boff[bt] = (uint32_t)(16384 + (wn * 64 + bt * 16 + lrow) * 128);

    float acc[2][8][4];
#pragma unroll
    for (int i = 0; i < 2; i++)
#pragma unroll
        for (int j = 0; j < 8; j++)
#pragma unroll
            for (int q = 0; q < 4; q++) acc[i][j][q] = 0.f;

    {
#pragma unroll
        for (int i = 0; i < 4; i++) {
            int idx = i * 256 + tid;
            int row = idx >> 3, c = idx & 7;
            uint32_t so = (uint32_t)(row * 128 + ((c * 16) ^ ((row & 7) << 4)));
            CPA(sb + so, Ag + (long)row * KEXT + c * 8);
            CPA(sb + 16384 + so, Bg + (long)row * KEXT + c * 8);
        }
        CPA_COMMIT();
    }

    for (int s = 0; s < NSTAGE; s++) {
        CPA_WAIT0();
        __syncthreads();
        if (s + 1 < NSTAGE) {
            const uint32_t dstb = sb + ((s + 1) & 1) * 32768;
            const long kb = (long)(s + 1) * 64;
#pragma unroll
            for (int i = 0; i < 4; i++) {
                int idx = i * 256 + tid;
                int row = idx >> 3, c = idx & 7;
                uint32_t so = (uint32_t)(row * 128 + ((c * 16) ^ ((row & 7) << 4)));
                CPA(dstb + so, Ag + (long)row * KEXT + kb + c * 8);
                CPA(dstb + 16384 + so, Bg + (long)row * KEXT + kb + c * 8);
            }
            CPA_COMMIT();
        }

        const uint32_t sbase = sb + (s & 1) * 32768;
#pragma unroll
        for (int kk = 0; kk < 4; kk++) {
            const uint32_t kb = (uint32_t)(kk * 32 + lkb) ^ xorp;
            uint32_t a0[4], a1[4];
            ldm4(a0, sbase + aoff[0] + kb);
            ldm4(a1, sbase + aoff[1] + kb);
#pragma unroll
            for (int bt = 0; bt < 4; bt++) {
                uint32_t bm[4];
                ldm4(bm, sbase + boff[bt] + kb);
                mma16816(acc[0][2 * bt],     a0, bm[0], bm[2]);
                mma16816(acc[1][2 * bt],     a1, bm[0], bm[2]);
                mma16816(acc[0][2 * bt + 1], a0, bm[1], bm[3]);
                mma16816(acc[1][2 * bt + 1], a1, bm[1], bm[3]);
            }
        }
        __syncthreads();
    }

    // epilogue
    const int crow0 = lane >> 2;
    const int ccol = (lane & 3) * 2;
#pragma unroll
    for (int mt = 0; mt < 2; mt++) {
#pragma unroll
        for (int h = 0; h < 2; h++) {
            const int m = m0 + wm * 32 + mt * 16 + crow0 + h * 8;
            if (EPI == 0) {
#pragma unroll
                for (int nt = 0; nt < 8; nt++) {
                    const int n = n0 + wn * 64 + nt * 8 + ccol;
                    float vx = acc[mt][nt][h * 2 + 0] + bias[n];
                    float vy = acc[mt][nt][h * 2 + 1] + bias[n + 1];
                    g_ep2[(long)m * 256 + (n >> 1)] = __floats2half2_rn(vx, vy);
                }
            } else if (EPI == 2) {
                if (m < Mreal) {
                    int t = (m >> 6) + 1;
                    int b = m & 63;
                    float* crow = C + (long)b * (TT * VV) + (long)t * VV;
#pragma unroll
                    for (int nt = 0; nt < 8; nt++) {
                        const int n = n0 + wn * 64 + nt * 8 + ccol;
                        if (n < Nreal) {
                            float2 o;
                            o.x = acc[mt][nt][h * 2 + 0] + bias[n];
                            o.y = acc[mt][nt][h * 2 + 1] + bias[n + 1];
                            *reinterpret_cast<float2*>(crow + n) = o;
                        }
                    }
                }
            } else {
                float* crow = C + (long)m * Nld;
#pragma unroll
                for (int nt = 0; nt < 8; nt++) {
                    const int n = n0 + wn * 64 + nt * 8 + ccol;
                    float2 o;
                    o.x = acc[mt][nt][h * 2 + 0] + bias[n];
                    o.y = acc[mt][nt][h * 2 + 1] + bias[n + 1];
                    *reinterpret_cast<float2*>(crow + n) = o;
                }
            }
        }
    }
}

// ---------------- conversion kernels ----------------
// feats: -> Aext (bf16 hi/hi/lo) AND -> g_feats2 (half2), one pass
__global__ void k_cvt_feats(const float* __restrict__ src, int n) {
    int i = blockIdx.x * 256 + threadIdx.x;
    if (i < n) {
        int row = i >> 9, k = i & 511;
        float x = src[i];
        __nv_bfloat16 h = __float2bfloat16(x);
        __nv_bfloat16 l = __float2bfloat16(x - __bfloat162float(h));
        __nv_bfloat16* d = g_Aext + (long)row * KEXT + k;
        d[0] = h; d[512] = h; d[1024] = l;
        reinterpret_cast<__half*>(g_feats2)[i] = __float2half(x);
    }
}

__global__ void k_cvt_ext(const float* __restrict__ src, __nv_bfloat16* __restrict__ dst, int n) {
    int i = blockIdx.x * 256 + threadIdx.x;
    if (i < n) {
        int row = i >> 9, k = i & 511;
        float x = src[i];
        __nv_bfloat16 h = __float2bfloat16(x);
        __nv_bfloat16 l = __float2bfloat16(x - __bfloat162float(h));
        __nv_bfloat16* d = dst + (long)row * KEXT + k;
        d[0] = h; d[512] = h; d[1024] = l;
    }
}

__global__ void k_gather_emb(const int* __restrict__ captions, const float* __restrict__ emb) {
    int i = blockIdx.x * 256 + threadIdx.x;
    if (i < 1856 * 512) {
        int rrow = i >> 9, d = i & 511;
        int t = rrow >> 6, b = rrow & 63;
        int tok = captions[b * TT + t];
        float x = emb[(long)tok * 512 + d];
        __nv_bfloat16 h = __float2bfloat16(x);
        __nv_bfloat16 l = __float2bfloat16(x - __bfloat162float(h));
        __nv_bfloat16* dd = g_Eext + (long)rrow * KEXT + d;
        dd[0] = h; dd[512] = h; dd[1024] = l;
    }
}

__global__ void k_tsp_ext(const float* __restrict__ src, __nv_bfloat16* __restrict__ dst,
                          int N, int Npad) {
    __shared__ float t[32][33];
    int n0 = blockIdx.x * 32, k0 = blockIdx.y * 32;
    int tx = threadIdx.x, ty = threadIdx.y;
#pragma unroll
    for (int i = 0; i < 32; i += 8) {
        int k = k0 + ty + i, n = n0 + tx;
        t[ty + i][tx] = (n < N) ? src[(long)k * N + n] : 0.f;
    }
    __syncthreads();
#pragma unroll
    for (int i = 0; i < 32; i += 8) {
        int n = n0 + ty + i, k = k0 + tx;
        if (n < Npad) {
            float x = t[tx][ty + i];
            __nv_bfloat16 h = __float2bfloat16(x);
            __nv_bfloat16 l = __float2bfloat16(x - __bfloat162float(h));
            __nv_bfloat16* d = dst + (long)n * KEXT + k;
            d[0] = h; d[512] = l; d[1024] = h;
        }
    }
}

// ---------------- packed f32x2 SIMT GEMM (gates, K=1024 over [ctx|h]) ----------------
__device__ __forceinline__ unsigned long long pack2(float x) {
    unsigned long long r;
    asm("mov.b64 %0, {%1, %1};" : "=l"(r) : "f"(x));
    return r;
}
__device__ __forceinline__ void fma2(unsigned long long& d, unsigned long long a, unsigned long long b) {
    asm("fma.rn.f32x2 %0, %1, %2, %0;" : "+l"(d) : "l"(a), "l"(b));
}
__device__ __forceinline__ float2 unpack2(unsigned long long v) {
    float2 r;
    asm("mov.b64 {%0, %1}, %2;" : "=f"(r.x), "=f"(r.y) : "l"(v));
    return r;
}

__global__ void __launch_bounds__(256) gemm_gates(
    const float* __restrict__ A, const float* __restrict__ B,
    float* __restrict__ C, int N, int lda, int kLen)
{
    __shared__ float As[2][16][64];
    __shared__ float Bs[2][16][128];

    const int tid = threadIdx.x;
    const int n0 = blockIdx.x * 128;
    const int kStart = blockIdx.z * kLen;
    const int tn = (tid & 15) * 8;
    const int tm = (tid >> 4) * 4;
    const int am = tid >> 2, ak = (tid & 3) * 4;
    const int bk = tid >> 4, bn = (tid & 15) * 8;

    const float* Aptr = A + (long)am * lda + kStart + ak;
    const float* Bptr = B + (long)(kStart + bk) * N + n0 + bn;

    unsigned long long acc[4][4];
#pragma unroll
    for (int i = 0; i < 4; i++) acc[i][0] = acc[i][1] = acc[i][2] = acc[i][3] = 0ull;

    const int nb = kLen / 16;
    float4 ar0, br0, br1;
    ar0 = *reinterpret_cast<const float4*>(Aptr);
    br0 = *reinterpret_cast<const float4*>(Bptr);
    br1 = *reinterpret_cast<const float4*>(Bptr + 4);
    As[0][ak + 0][am] = ar0.x; As[0][ak + 1][am] = ar0.y;
    As[0][ak + 2][am] = ar0.z; As[0][ak + 3][am] = ar0.w;
    *reinterpret_cast<float4*>(&Bs[0][bk][bn]) = br0;
    *reinterpret_cast<float4*>(&Bs[0][bk][bn + 4]) = br1;
    __syncthreads();

    for (int ib = 0; ib < nb; ib++) {
        const int cur = ib & 1;
        const bool more = (ib + 1) < nb;
        if (more) {
            ar0 = *reinterpret_cast<const float4*>(Aptr + (ib + 1) * 16);
            const float* bp = Bptr + (long)((ib + 1) * 16) * N;
            br0 = *reinterpret_cast<const float4*>(bp);
            br1 = *reinterpret_cast<const float4*>(bp + 4);
        }
#pragma unroll
        for (int kk = 0; kk < 16; kk++) {
            unsigned long long ad[4];
            float4 af = *reinterpret_cast<const float4*>(&As[cur][kk][tm]);
            ad[0] = pack2(af.x); ad[1] = pack2(af.y); ad[2] = pack2(af.z); ad[3] = pack2(af.w);
            ulonglong2 bv0 = *reinterpret_cast<const ulonglong2*>(&Bs[cur][kk][tn]);
            ulonglong2 bv1 = *reinterpret_cast<const ulonglong2*>(&Bs[cur][kk][tn + 4]);
#pragma unroll
            for (int i = 0; i < 4; i++) {
                fma2(acc[i][0], ad[i], bv0.x);
                fma2(acc[i][1], ad[i], bv0.y);
                fma2(acc[i][2], ad[i], bv1.x);
                fma2(acc[i][3], ad[i], bv1.y);
            }
        }
        if (more) {
            const int nxt = cur ^ 1;
            As[nxt][ak + 0][am] = ar0.x; As[nxt][ak + 1][am] = ar0.y;
            As[nxt][ak + 2][am] = ar0.z; As[nxt][ak + 3][am] = ar0.w;
            *reinterpret_cast<float4*>(&Bs[nxt][bk][bn]) = br0;
            *reinterpret_cast<float4*>(&Bs[nxt][bk][bn + 4]) = br1;
        }
        __syncthreads();
    }

#pragma unroll
    for (int i = 0; i < 4; i++) {
        float* crow = C + (long)(tm + i) * N;
        float2 v[4];
        v[0] = unpack2(acc[i][0]); v[1] = unpack2(acc[i][1]);
        v[2] = unpack2(acc[i][2]); v[3] = unpack2(acc[i][3]);
#pragma unroll
        for (int j = 0; j < 4; j++) {
            int gn = n0 + tn + 2 * j;
            atomicAdd(crow + gn, v[j].x);
            atomicAdd(crow + gn + 1, v[j].y);
        }
    }
}

// ---------------- small kernels ----------------
__global__ void k_zero_t0(float* __restrict__ out) {
    int idx = blockIdx.x * 256 + threadIdx.x;
    if (idx < BATCH * VV) {
        int b = idx / VV, v = idx - b * VV;
        out[(long)b * (TT * VV) + v] = 0.f;
    }
}

__global__ void k_init_hc(const float* __restrict__ pooled,
                          const float* __restrict__ Wh, const float* __restrict__ bh,
                          const float* __restrict__ Wc, const float* __restrict__ bc) {
    int b = blockIdx.y;
    int j = blockIdx.x * 256 + threadIdx.x;
    __shared__ float pr[512];
    pr[threadIdx.x] = pooled[b * 512 + threadIdx.x];
    pr[threadIdx.x + 256] = pooled[b * 512 + threadIdx.x + 256];
    __syncthreads();
    float a0 = 0, a1 = 0, a2 = 0, a3 = 0;
    const float* W = (j < 512) ? (Wh + j) : (Wc + j - 512);
    for (int k = 0; k < 512; k += 4) {
        a0 += pr[k] * W[k * 512];
        a1 += pr[k + 1] * W[(k + 1) * 512];
        a2 += pr[k + 2] * W[(k + 2) * 512];
        a3 += pr[k + 3] * W[(k + 3) * 512];
    }
    float s = (a0 + a1) + (a2 + a3);
    if (j < 512) g_h[b * 512 + j] = tanhf(s + bh[j]);
    else         g_c[b * 512 + (j - 512)] = tanhf(s + bc[j - 512]);
}

__global__ void k_wcat(const float* __restrict__ Wih, const float* __restrict__ Whh,
                       const float* __restrict__ bih, const float* __restrict__ bhh) {
    int idx = blockIdx.x * 256 + threadIdx.x;
    if (idx < 1536 * 2048) {
        int k = idx >> 11, n = idx & 2047;
        g_Wcat[idx] = (k < 1024) ? Wih[idx] : Whh[(k - 1024) * 2048 + n];
    }
    if (idx < 2048) g_bias4[idx] = bih[idx] + bhh[idx];
}

// per step: dec_proj/gate (blocks 0..255); h->x copy + gates init from gpre (blocks 256..)
__global__ void k_step1(const float* __restrict__ Wd, const float* __restrict__ bd,
                        const float* __restrict__ Wb, const float* __restrict__ bb, int tm1) {
    int blk = blockIdx.x;
    if (blk < 256) {
        int b = blk >> 2;
        int j = (blk & 3) * 256 + threadIdx.x;
        __shared__ float hr[512];
        hr[threadIdx.x] = g_h[b * 512 + threadIdx.x];
        hr[threadIdx.x + 256] = g_h[b * 512 + threadIdx.x + 256];
        __syncthreads();
        float a0 = 0, a1 = 0, a2 = 0, a3 = 0;
        const float* W = (j < 512) ? (Wd + j) : (Wb + j - 512);
        for (int k = 0; k < 512; k += 4) {
            a0 += hr[k] * W[k * 512];
            a1 += hr[k + 1] * W[(k + 1) * 512];
            a2 += hr[k + 2] * W[(k + 2) * 512];
            a3 += hr[k + 3] * W[(k + 3) * 512];
        }
        float s = (a0 + a1) + (a2 + a3);
        if (j < 512) g_hgate[b * 1024 + j] = s + bd[j];
        else         g_hgate[b * 1024 + j] = sigf(s + bb[j - 512]);
    } else {
        int idx = (blk - 256) * 256 + threadIdx.x;   // < 163840
        if (idx < 32768) {
            int b = idx >> 9, k = idx & 511;
            g_x[b * 1536 + 1024 + k] = g_h[idx];
        } else {
            int rr = idx - 32768;                    // < 131072
            g_gates[rr] = g_gpre[(long)tm1 * 131072 + rr];
        }
    }
}

// attention scores: half2 enc_proj, fp32 math
__global__ void k_att(const float* __restrict__ wf, const float* __restrict__ bf) {
    int b = blockIdx.x / 25;
    int pc = blockIdx.x % 25;
    __shared__ float dp[512], wfs[512];
    dp[threadIdx.x] = g_hgate[b * 1024 + threadIdx.x];
    dp[threadIdx.x + 256] = g_hgate[b * 1024 + threadIdx.x + 256];
    wfs[threadIdx.x] = wf[threadIdx.x];
    wfs[threadIdx.x + 256] = wf[threadIdx.x + 256];
    __syncthreads();
    int p = pc * 8 + (threadIdx.x >> 5);
    int lane = threadIdx.x & 31;
    if (p < PP) {
        const __half2* ep = g_ep2 + ((long)(b * PP + p)) * 256;
        float acc = 0.f;
#pragma unroll
        for (int i = 0; i < 8; i++) {
            int h2i = i * 32 + lane;            // half2 index: covers a = 2*h2i, 2*h2i+1
            float2 e = __half22float2(ep[h2i]);
            int a = 2 * h2i;
            acc += tanh_a(e.x + dp[a]) * wfs[a];
            acc += tanh_a(e.y + dp[a + 1]) * wfs[a + 1];
        }
#pragma unroll
        for (int off = 16; off; off >>= 1) acc += __shfl_down_sync(0xffffffffu, acc, off);
        if (lane == 0) g_scores[b * PP + p] = acc + bf[0];
    }
}

// softmax + gated ctx; ONE block per batch, each thread owns one half2 column (2 d's)
__global__ void k_softmax_ctx() {
    int b = blockIdx.x;
    int tid = threadIdx.x;
    __shared__ float sc[256];
    __shared__ float red[256];
    float v = (tid < PP) ? g_scores[b * PP + tid] : -1e30f;
    red[tid] = v;
    __syncthreads();
    for (int s = 128; s > 0; s >>= 1) {
        if (tid < s) red[tid] = fmaxf(red[tid], red[tid + s]);
        __syncthreads();
    }
    float mx = red[0];
    __syncthreads();
    float e = (tid < PP) ? expf(v - mx) : 0.f;
    red[tid] = e;
    __syncthreads();
    for (int s = 128; s > 0; s >>= 1) {
        if (tid < s) red[tid] += red[tid + s];
        __syncthreads();
    }
    sc[tid] = e / red[0];
    __syncthreads();

    const __half2* fp = g_feats2 + (long)b * PP * 256 + tid;
    float ax = 0.f, ay = 0.f;
#pragma unroll 4
    for (int p = 0; p < PP; p++) {
        float2 f = __half22float2(fp[(long)p * 256]);
        float a = sc[p];
        ax += a * f.x;
        ay += a * f.y;
    }
    int d = tid * 2;
    float2 o;
    o.x = ax * g_hgate[b * 1024 + 512 + d];
    o.y = ay * g_hgate[b * 1024 + 512 + d + 1];
    *reinterpret_cast<float2*>(&g_x[b * 1536 + 512 + d]) = o;
}

__global__ void k_lstm(int tm1) {
    int idx = blockIdx.x * 256 + threadIdx.x;
    int b = idx >> 9, d = idx & 511;
    const float* gg = g_gates + b * 2048;
    float ig = sigf(gg[d]);
    float fg = sigf(gg[512 + d]);
    float gv = tanhf(gg[1024 + d]);
    float og = sigf(gg[1536 + d]);
    float c2 = fg * g_c[idx] + ig * gv;
    float h2 = og * tanhf(c2);
    g_c[idx] = c2;
    g_h[idx] = h2;
    g_H[((long)tm1 * BATCH + b) * 512 + d] = h2;
}

// ---------------- launcher ----------------
extern "C" void kernel_launch(void* const* d_in, const int* in_sizes, int n_in,
                              void* d_out, int out_size) {
    const float* encoder_feats  = (const float*)d_in[0];
    const float* encoder_pooled = (const float*)d_in[1];
    const int*   captions       = (const int*)d_in[2];
    const float* We_att  = (const float*)d_in[3];
    const float* be_att  = (const float*)d_in[4];
    const float* Wd_att  = (const float*)d_in[5];
    const float* bd_att  = (const float*)d_in[6];
    const float* wf_att  = (const float*)d_in[7];
    const float* bf_att  = (const float*)d_in[8];
    const float* emb_table = (const float*)d_in[9];
    const float* W_ih = (const float*)d_in[10];
    const float* W_hh = (const float*)d_in[11];
    const float* b_ih = (const float*)d_in[12];
    const float* b_hh = (const float*)d_in[13];
    const float* W_init_h = (const float*)d_in[14];
    const float* b_init_h = (const float*)d_in[15];
    const float* W_init_c = (const float*)d_in[16];
    const float* b_init_c = (const float*)d_in[17];
    const float* W_fc  = (const float*)d_in[18];
    const float* b_fc  = (const float*)d_in[19];
    const float* W_beta = (const float*)d_in[20];
    const float* b_beta = (const float*)d_in[21];
    float* out = (float*)d_out;

    void* p;
    cudaGetSymbolAddress(&p, g_x);        float* x_ptr = (float*)p;
    cudaGetSymbolAddress(&p, g_Wcat);     float* wcat_ptr = (float*)p;
    cudaGetSymbolAddress(&p, g_gates);    float* gates_ptr = (float*)p;
    cudaGetSymbolAddress(&p, g_bias4);    float* bias4_ptr = (float*)p;
    cudaGetSymbolAddress(&p, g_gpre);     float* gpre_ptr = (float*)p;
    cudaGetSymbolAddress(&p, g_H);        float* H_ptr = (float*)p;
    cudaGetSymbolAddress(&p, g_Aext);     __nv_bfloat16* Aext = (__nv_bfloat16*)p;
    cudaGetSymbolAddress(&p, g_Bext);     __nv_bfloat16* Bext = (__nv_bfloat16*)p;
    cudaGetSymbolAddress(&p, g_Wext);     __nv_bfloat16* Wext = (__nv_bfloat16*)p;
    cudaGetSymbolAddress(&p, g_Wihext);   __nv_bfloat16* Wihext = (__nv_bfloat16*)p;
    cudaGetSymbolAddress(&p, g_Eext);     __nv_bfloat16* Eext = (__nv_bfloat16*)p;

    const int SMEM = 64 * 1024;
    cudaFuncSetAttribute(mma_gemm<0>, cudaFuncAttributeMaxDynamicSharedMemorySize, SMEM);
    cudaFuncSetAttribute(mma_gemm<1>, cudaFuncAttributeMaxDynamicSharedMemorySize, SMEM);
    cudaFuncSetAttribute(mma_gemm<2>, cudaFuncAttributeMaxDynamicSharedMemorySize, SMEM);

    // prologue
    k_zero_t0<<<(BATCH * VV + 255) / 256, 256>>>(out);
    k_init_hc<<<dim3(4, BATCH), 256>>>(encoder_pooled, W_init_h, b_init_h, W_init_c, b_init_c);
    k_wcat<<<(1536 * 2048 + 255) / 256, 256>>>(W_ih, W_hh, b_ih, b_hh);
    k_tsp_ext<<<dim3(940, 16), dim3(32, 8)>>>(W_fc, Bext, VV, NPAD);
    k_tsp_ext<<<dim3(16, 16), dim3(32, 8)>>>(We_att, Wext, 512, 512);
    k_tsp_ext<<<dim3(64, 16), dim3(32, 8)>>>(W_ih, Wihext, 2048, 2048);
    k_cvt_feats<<<(12544 * 512 + 255) / 256, 256>>>(encoder_feats, 12544 * 512);
    k_gather_emb<<<(1856 * 512 + 255) / 256, 256>>>(captions, emb_table);
    // enc_proj -> g_ep2 (half2)
    mma_gemm<0><<<dim3(4, 98), 256, SMEM>>>(Aext, Wext, nullptr, be_att, 512, 12544, 512);
    // gates_pre = emb @ W_ih[0:512] + (b_ih + b_hh)
    mma_gemm<1><<<dim3(16, 15), 256, SMEM>>>(Eext, Wihext, gpre_ptr, bias4_ptr, 2048, 1920, 2048);

    // recurrence (5 launches/step, R10 structure)
    for (int t = 1; t < TT; t++) {
        int tm1 = t - 1;
        k_step1<<<896, 256>>>(Wd_att, bd_att, W_beta, b_beta, tm1);
        k_att<<<64 * 25, 256>>>(wf_att, bf_att);
        k_softmax_ctx<<<64, 256>>>();
        gemm_gates<<<dim3(16, 1, 8), 256>>>(x_ptr + 512, wcat_ptr + 512 * 2048, gates_ptr,
                                            2048, 1536, 128);
        k_lstm<<<128, 256>>>(tm1);
    }

    // vocab projection (m varies fastest: B L2-resident)
    k_cvt_ext<<<(1920 * 512 + 255) / 256, 256>>>(H_ptr, Aext, 1920 * 512);
    mma_gemm<2><<<dim3(15, NPAD / 128), 256, SMEM>>>(Aext, Bext, out, b_fc,
                                                     VV, (TT - 1) * BATCH, VV);
}

// round 13
// speedup vs baseline: 1.0945x; 1.0029x over previous
#include <cuda_runtime.h>
#include <cuda_bf16.h>
#include <cuda_fp16.h>
#include <math.h>
#include <stdint.h>

// Problem dims
#define BATCH 64
#define PP    196
#define TT    30
#define VV    30000
#define NPAD  30080
#define KEXT  1536      // 3 x 512 (hi*hi + hi*lo + lo*hi)

// ---------------- device scratch ----------------
__device__ float g_h[BATCH * 512];               // initial h only
__device__ float g_c2[2][BATCH * 512];           // double-buffered cell state
__device__ float g_hgate[BATCH * 1024];
__device__ float g_scores[BATCH * PP];
__device__ float g_x[BATCH * 1536];
__device__ float g_gates2[2][BATCH * 2048];      // double-buffered gates
__device__ float g_Wcat[1536 * 2048];
__device__ float g_bias4[2048];
__device__ float g_gpre[1920 * 2048];            // precomputed emb@W_ih + bias
__device__ float g_H[TT * BATCH * 512];

__device__ __half2 g_ep2[12544 * 256];           // enc_proj half2
__device__ __half2 g_feats2[12544 * 256];        // encoder_feats half2

__device__ __nv_bfloat16 g_Aext[12544 * KEXT];   // feats ext; reused for H ext
__device__ __nv_bfloat16 g_Bext[NPAD * KEXT];    // W_fc^T ext
__device__ __nv_bfloat16 g_Wext[512 * KEXT];     // We_att^T ext
__device__ __nv_bfloat16 g_Wihext[2048 * KEXT];  // W_ih[0:512]^T ext
__device__ __nv_bfloat16 g_Eext[1920 * KEXT];    // gathered emb ext

__device__ __forceinline__ float sigf(float x) { return 1.f / (1.f + expf(-x)); }
__device__ __forceinline__ float tanh_a(float x) {
    float y; asm("tanh.approx.f32 %0, %1;" : "=f"(y) : "f"(x)); return y;
}
__device__ __forceinline__ uint32_t smem_u32(const void* p) {
    uint32_t a;
    asm("{ .reg .u64 t; cvta.to.shared.u64 t, %1; cvt.u32.u64 %0, t; }" : "=r"(a) : "l"(p));
    return a;
}

// ---------------- mma.sync bf16 GEMM ----------------
#define NSTAGE (KEXT / 64)   // 24

__device__ __forceinline__ void ldm4(uint32_t* r, uint32_t addr) {
    asm volatile("ldmatrix.sync.aligned.m8n8.x4.shared.b16 {%0,%1,%2,%3}, [%4];"
        : "=r"(r[0]), "=r"(r[1]), "=r"(r[2]), "=r"(r[3]) : "r"(addr));
}
__device__ __forceinline__ void mma16816(float* c, const uint32_t* a, uint32_t b0, uint32_t b1) {
    asm volatile("mma.sync.aligned.m16n8k16.row.col.f32.bf16.bf16.f32 "
        "{%0,%1,%2,%3}, {%4,%5,%6,%7}, {%8,%9}, {%0,%1,%2,%3};"
        : "+f"(c[0]), "+f"(c[1]), "+f"(c[2]), "+f"(c[3])
        : "r"(a[0]), "r"(a[1]), "r"(a[2]), "r"(a[3]), "r"(b0), "r"(b1));
}
#define CPA(saddr, gaddr) \
    asm volatile("cp.async.cg.shared.global [%0], [%1], 16;" :: "r"(saddr), "l"(gaddr))
#define CPA_COMMIT() asm volatile("cp.async.commit_group;")
#define CPA_WAIT0()  asm volatile("cp.async.wait_group 0;")

// EPI 0: enc_proj -> g_ep2 (half2, +bias). EPI 1: fp32 C row-major + bias.
// EPI 2: vocab scatter + bias (m on blockIdx.x -> B stays L2-resident).
template <int EPI>
__global__ void __launch_bounds__(256) mma_gemm(
    const __nv_bfloat16* __restrict__ Aext, const __nv_bfloat16* __restrict__ Bext,
    float* __restrict__ C, const float* __restrict__ bias,
    int Nld, int Mreal, int Nreal)
{
    extern __shared__ char sm[];
    const uint32_t sb = smem_u32(sm);
    const int tid = threadIdx.x;
    const int m0 = (EPI == 2 ? blockIdx.x : blockIdx.y) * 128;
    const int n0 = (EPI == 2 ? blockIdx.y : blockIdx.x) * 128;

    const __nv_bfloat16* Ag = Aext + (long)m0 * KEXT;
    const __nv_bfloat16* Bg = Bext + (long)n0 * KEXT;

    const int wid = tid >> 5, lane = tid & 31;
    const int wm = wid & 3, wn = wid >> 2;
    const int g = lane >> 3, r = lane & 7;
    const int lrow = (g & 1) * 8 + r;
    const uint32_t lkb = (g >> 1) * 16;
    const uint32_t xorp = (uint32_t)(r << 4);

    uint32_t aoff[2], boff[4];
#pragma unroll
    for (int mt = 0; mt < 2; mt++) aoff[mt] = (uint32_t)((wm * 32 + mt * 16 + lrow) * 128);
#pragma unroll
    for (int bt = 0; bt < 4; bt++) boff[bt] = (uint32_t)(16384 + (wn * 64 + bt * 16 + lrow) * 128);

    float acc[2][8][4];
#pragma unroll
    for (int i = 0; i < 2; i++)
#pragma unroll
        for (int j = 0; j < 8; j++)
#pragma unroll
            for (int q = 0; q < 4; q++) acc[i][j][q] = 0.f;

    {
#pragma unroll
        for (int i = 0; i < 4; i++) {
            int idx = i * 256 + tid;
            int row = idx >> 3, c = idx & 7;
            uint32_t so = (uint32_t)(row * 128 + ((c * 16) ^ ((row & 7) << 4)));
            CPA(sb + so, Ag + (long)row * KEXT + c * 8);
            CPA(sb + 16384 + so, Bg + (long)row * KEXT + c * 8);
        }
        CPA_COMMIT();
    }

    for (int s = 0; s < NSTAGE; s++) {
        CPA_WAIT0();
        __syncthreads();
        if (s + 1 < NSTAGE) {
            const uint32_t dstb = sb + ((s + 1) & 1) * 32768;
            const long kb = (long)(s + 1) * 64;
#pragma unroll
            for (int i = 0; i < 4; i++) {
                int idx = i * 256 + tid;
                int row = idx >> 3, c = idx & 7;
                uint32_t so = (uint32_t)(row * 128 + ((c * 16) ^ ((row & 7) << 4)));
                CPA(dstb + so, Ag + (long)row * KEXT + kb + c * 8);
                CPA(dstb + 16384 + so, Bg + (long)row * KEXT + kb + c * 8);
            }
            CPA_COMMIT();
        }

        const uint32_t sbase = sb + (s & 1) * 32768;
#pragma unroll
        for (int kk = 0; kk < 4; kk++) {
            const uint32_t kb = (uint32_t)(kk * 32 + lkb) ^ xorp;
            uint32_t a0[4], a1[4];
            ldm4(a0, sbase + aoff[0] + kb);
            ldm4(a1, sbase + aoff[1] + kb);
#pragma unroll
            for (int bt = 0; bt < 4; bt++) {
                uint32_t bm[4];
                ldm4(bm, sbase + boff[bt] + kb);
                mma16816(acc[0][2 * bt],     a0, bm[0], bm[2]);
                mma16816(acc[1][2 * bt],     a1, bm[0], bm[2]);
                mma16816(acc[0][2 * bt + 1], a0, bm[1], bm[3]);
                mma16816(acc[1][2 * bt + 1], a1, bm[1], bm[3]);
            }
        }
        __syncthreads();
    }

    // epilogue
    const int crow0 = lane >> 2;
    const int ccol = (lane & 3) * 2;
#pragma unroll
    for (int mt = 0; mt < 2; mt++) {
#pragma unroll
        for (int h = 0; h < 2; h++) {
            const int m = m0 + wm * 32 + mt * 16 + crow0 + h * 8;
            if (EPI == 0) {
#pragma unroll
                for (int nt = 0; nt < 8; nt++) {
                    const int n = n0 + wn * 64 + nt * 8 + ccol;
                    float vx = acc[mt][nt][h * 2 + 0] + bias[n];
                    float vy = acc[mt][nt][h * 2 + 1] + bias[n + 1];
                    g_ep2[(long)m * 256 + (n >> 1)] = __floats2half2_rn(vx, vy);
                }
            } else if (EPI == 2) {
                if (m < Mreal) {
                    int t = (m >> 6) + 1;
                    int b = m & 63;
                    float* crow = C + (long)b * (TT * VV) + (long)t * VV;
#pragma unroll
                    for (int nt = 0; nt < 8; nt++) {
                        const int n = n0 + wn * 64 + nt * 8 + ccol;
                        if (n < Nreal) {
                            float2 o;
                            o.x = acc[mt][nt][h * 2 + 0] + bias[n];
                            o.y = acc[mt][nt][h * 2 + 1] + bias[n + 1];
                            *reinterpret_cast<float2*>(crow + n) = o;
                        }
                    }
                }
            } else {
                float* crow = C + (long)m * Nld;
#pragma unroll
                for (int nt = 0; nt < 8; nt++) {
                    const int n = n0 + wn * 64 + nt * 8 + ccol;
                    float2 o;
                    o.x = acc[mt][nt][h * 2 + 0] + bias[n];
                    o.y = acc[mt][nt][h * 2 + 1] + bias[n + 1];
                    *reinterpret_cast<float2*>(crow + n) = o;
                }
            }
        }
    }
}

// ---------------- conversion kernels ----------------
__global__ void k_cvt_feats(const float* __restrict__ src, int n) {
    int i = blockIdx.x * 256 + threadIdx.x;
    if (i < n) {
        int row = i >> 9, k = i & 511;
        float x = src[i];
        __nv_bfloat16 h = __float2bfloat16(x);
        __nv_bfloat16 l = __float2bfloat16(x - __bfloat162float(h));
        __nv_bfloat16* d = g_Aext + (long)row * KEXT + k;
        d[0] = h; d[512] = h; d[1024] = l;
        reinterpret_cast<__half*>(g_feats2)[i] = __float2half(x);
    }
}

__global__ void k_cvt_ext(const float* __restrict__ src, __nv_bfloat16* __restrict__ dst, int n) {
    int i = blockIdx.x * 256 + threadIdx.x;
    if (i < n) {
        int row = i >> 9, k = i & 511;
        float x = src[i];
        __nv_bfloat16 h = __float2bfloat16(x);
        __nv_bfloat16 l = __float2bfloat16(x - __bfloat162float(h));
        __nv_bfloat16* d = dst + (long)row * KEXT + k;
        d[0] = h; d[512] = h; d[1024] = l;
    }
}

__global__ void k_gather_emb(const int* __restrict__ captions, const float* __restrict__ emb) {
    int i = blockIdx.x * 256 + threadIdx.x;
    if (i < 1856 * 512) {
        int rrow = i >> 9, d = i & 511;
        int t = rrow >> 6, b = rrow & 63;
        int tok = captions[b * TT + t];
        float x = emb[(long)tok * 512 + d];
        __nv_bfloat16 h = __float2bfloat16(x);
        __nv_bfloat16 l = __float2bfloat16(x - __bfloat162float(h));
        __nv_bfloat16* dd = g_Eext + (long)rrow * KEXT + d;
        dd[0] = h; dd[512] = h; dd[1024] = l;
    }
}

__global__ void k_tsp_ext(const float* __restrict__ src, __nv_bfloat16* __restrict__ dst,
                          int N, int Npad) {
    __shared__ float t[32][33];
    int n0 = blockIdx.x * 32, k0 = blockIdx.y * 32;
    int tx = threadIdx.x, ty = threadIdx.y;
#pragma unroll
    for (int i = 0; i < 32; i += 8) {
        int k = k0 + ty + i, n = n0 + tx;
        t[ty + i][tx] = (n < N) ? src[(long)k * N + n] : 0.f;
    }
    __syncthreads();
#pragma unroll
    for (int i = 0; i < 32; i += 8) {
        int n = n0 + ty + i, k = k0 + tx;
        if (n < Npad) {
            float x = t[tx][ty + i];
            __nv_bfloat16 h = __float2bfloat16(x);
            __nv_bfloat16 l = __float2bfloat16(x - __bfloat162float(h));
            __nv_bfloat16* d = dst + (long)n * KEXT + k;
            d[0] = h; d[512] = l; d[1024] = h;
        }
    }
}

// ---------------- packed f32x2 SIMT GEMM ----------------
__device__ __forceinline__ unsigned long long pack2(float x) {
    unsigned long long r;
    asm("mov.b64 %0, {%1, %1};" : "=l"(r) : "f"(x));
    return r;
}
__device__ __forceinline__ void fma2(unsigned long long& d, unsigned long long a, unsigned long long b) {
    asm("fma.rn.f32x2 %0, %1, %2, %0;" : "+l"(d) : "l"(a), "l"(b));
}
__device__ __forceinline__ float2 unpack2(unsigned long long v) {
    float2 r;
    asm("mov.b64 {%0, %1}, %2;" : "=f"(r.x), "=f"(r.y) : "l"(v));
    return r;
}

__global__ void __launch_bounds__(256) gemm_gates(
    const float* __restrict__ A, const float* __restrict__ B,
    float* __restrict__ C, int N, int lda, int kLen)
{
    __shared__ float As[2][16][64];
    __shared__ float Bs[2][16][128];

    const int tid = threadIdx.x;
    const int n0 = blockIdx.x * 128;
    const int kStart = blockIdx.z * kLen;
    const int tn = (tid & 15) * 8;
    const int tm = (tid >> 4) * 4;
    const int am = tid >> 2, ak = (tid & 3) * 4;
    const int bk = tid >> 4, bn = (tid & 15) * 8;

    const float* Aptr = A + (long)am * lda + kStart + ak;
    const float* Bptr = B + (long)(kStart + bk) * N + n0 + bn;

    unsigned long long acc[4][4];
#pragma unroll
    for (int i = 0; i < 4; i++) acc[i][0] = acc[i][1] = acc[i][2] = acc[i][3] = 0ull;

    const int nb = kLen / 16;
    float4 ar0, br0, br1;
    ar0 = *reinterpret_cast<const float4*>(Aptr);
    br0 = *reinterpret_cast<const float4*>(Bptr);
    br1 = *reinterpret_cast<const float4*>(Bptr + 4);
    As[0][ak + 0][am] = ar0.x; As[0][ak + 1][am] = ar0.y;
    As[0][ak + 2][am] = ar0.z; As[0][ak + 3][am] = ar0.w;
    *reinterpret_cast<float4*>(&Bs[0][bk][bn]) = br0;
    *reinterpret_cast<float4*>(&Bs[0][bk][bn + 4]) = br1;
    __syncthreads();

    for (int ib = 0; ib < nb; ib++) {
        const int cur = ib & 1;
        const bool more = (ib + 1) < nb;
        if (more) {
            ar0 = *reinterpret_cast<const float4*>(Aptr + (ib + 1) * 16);
            const float* bp = Bptr + (long)((ib + 1) * 16) * N;
            br0 = *reinterpret_cast<const float4*>(bp);
            br1 = *reinterpret_cast<const float4*>(bp + 4);
        }
#pragma unroll
        for (int kk = 0; kk < 16; kk++) {
            unsigned long long ad[4];
            float4 af = *reinterpret_cast<const float4*>(&As[cur][kk][tm]);
            ad[0] = pack2(af.x); ad[1] = pack2(af.y); ad[2] = pack2(af.z); ad[3] = pack2(af.w);
            ulonglong2 bv0 = *reinterpret_cast<const ulonglong2*>(&Bs[cur][kk][tn]);
            ulonglong2 bv1 = *reinterpret_cast<const ulonglong2*>(&Bs[cur][kk][tn + 4]);
#pragma unroll
            for (int i = 0; i < 4; i++) {
                fma2(acc[i][0], ad[i], bv0.x);
                fma2(acc[i][1], ad[i], bv0.y);
                fma2(acc[i][2], ad[i], bv1.x);
                fma2(acc[i][3], ad[i], bv1.y);
            }
        }
        if (more) {
            const int nxt = cur ^ 1;
            As[nxt][ak + 0][am] = ar0.x; As[nxt][ak + 1][am] = ar0.y;
            As[nxt][ak + 2][am] = ar0.z; As[nxt][ak + 3][am] = ar0.w;
            *reinterpret_cast<float4*>(&Bs[nxt][bk][bn]) = br0;
            *reinterpret_cast<float4*>(&Bs[nxt][bk][bn + 4]) = br1;
        }
        __syncthreads();
    }

#pragma unroll
    for (int i = 0; i < 4; i++) {
        float* crow = C + (long)(tm + i) * N;
        float2 v[4];
        v[0] = unpack2(acc[i][0]); v[1] = unpack2(acc[i][1]);
        v[2] = unpack2(acc[i][2]); v[3] = unpack2(acc[i][3]);
#pragma unroll
        for (int j = 0; j < 4; j++) {
            int gn = n0 + tn + 2 * j;
            atomicAdd(crow + gn, v[j].x);
            atomicAdd(crow + gn + 1, v[j].y);
        }
    }
}

// ---------------- small kernels ----------------
__global__ void k_zero_t0(float* __restrict__ out) {
    int idx = blockIdx.x * 256 + threadIdx.x;
    if (idx < BATCH * VV) {
        int b = idx / VV, v = idx - b * VV;
        out[(long)b * (TT * VV) + v] = 0.f;
    }
}

__global__ void k_init_hc(const float* __restrict__ pooled,
                          const float* __restrict__ Wh, const float* __restrict__ bh,
                          const float* __restrict__ Wc, const float* __restrict__ bc) {
    int b = blockIdx.y;
    int j = blockIdx.x * 256 + threadIdx.x;
    __shared__ float pr[512];
    pr[threadIdx.x] = pooled[b * 512 + threadIdx.x];
    pr[threadIdx.x + 256] = pooled[b * 512 + threadIdx.x + 256];
    __syncthreads();
    float a0 = 0, a1 = 0, a2 = 0, a3 = 0;
    const float* W = (j < 512) ? (Wh + j) : (Wc + j - 512);
    for (int k = 0; k < 512; k += 4) {
        a0 += pr[k] * W[k * 512];
        a1 += pr[k + 1] * W[(k + 1) * 512];
        a2 += pr[k + 2] * W[(k + 2) * 512];
        a3 += pr[k + 3] * W[(k + 3) * 512];
    }
    float s = (a0 + a1) + (a2 + a3);
    if (j < 512) g_h[b * 512 + j] = tanhf(s + bh[j]);
    else         g_c2[0][b * 512 + (j - 512)] = tanhf(s + bc[j - 512]);
}

__global__ void k_wcat(const float* __restrict__ Wih, const float* __restrict__ Whh,
                       const float* __restrict__ bih, const float* __restrict__ bhh) {
    int idx = blockIdx.x * 256 + threadIdx.x;
    if (idx < 1536 * 2048) {
        int k = idx >> 11, n = idx & 2047;
        g_Wcat[idx] = (k < 1024) ? Wih[idx] : Whh[(k - 1024) * 2048 + n];
    }
    if (idx < 2048) g_bias4[idx] = bih[idx] + bhh[idx];
}

// fused step head: (optional) LSTM of previous step + dec_proj/gate + gates init
// blocks 0..255: 4 per batch; blocks 256..767: gates[t&1] <- gpre[t-1]
__global__ void __launch_bounds__(256) k_stepf(
    const float* __restrict__ Wd, const float* __restrict__ bd,
    const float* __restrict__ Wb, const float* __restrict__ bb, int t)
{
    int blk = blockIdx.x;
    if (blk < 256) {
        int b = blk >> 2;
        int q = blk & 3;
        __shared__ float hr[512];
        if (t == 1) {
#pragma unroll
            for (int u = 0; u < 2; u++) {
                int d = threadIdx.x + u * 256;
                float h0 = g_h[b * 512 + d];
                hr[d] = h0;
                if (q == 0) g_x[b * 1536 + 1024 + d] = h0;
            }
        } else {
            const float* gg = g_gates2[(t - 1) & 1] + b * 2048;
            const float* cp = g_c2[(t - 2) & 1] + b * 512;
            float* cn = g_c2[(t - 1) & 1] + b * 512;
#pragma unroll
            for (int u = 0; u < 2; u++) {
                int d = threadIdx.x + u * 256;
                float ig = sigf(gg[d]);
                float fg = sigf(gg[512 + d]);
                float gv = tanhf(gg[1024 + d]);
                float og = sigf(gg[1536 + d]);
                float c2v = fg * cp[d] + ig * gv;
                float h2 = og * tanhf(c2v);
                hr[d] = h2;
                if (q == 0) {
                    cn[d] = c2v;
                    g_H[((long)(t - 2) * BATCH + b) * 512 + d] = h2;
                    g_x[b * 1536 + 1024 + d] = h2;
                }
            }
        }
        __syncthreads();
        int j = q * 256 + threadIdx.x;
        float a0 = 0, a1 = 0, a2 = 0, a3 = 0;
        const float* W = (j < 512) ? (Wd + j) : (Wb + j - 512);
        for (int k = 0; k < 512; k += 4) {
            a0 += hr[k] * W[k * 512];
            a1 += hr[k + 1] * W[(k + 1) * 512];
            a2 += hr[k + 2] * W[(k + 2) * 512];
            a3 += hr[k + 3] * W[(k + 3) * 512];
        }
        float s = (a0 + a1) + (a2 + a3);
        if (j < 512) g_hgate[b * 1024 + j] = s + bd[j];
        else         g_hgate[b * 1024 + j] = sigf(s + bb[j - 512]);
    } else {
        int idx = (blk - 256) * 256 + threadIdx.x;   // < 131072
        g_gates2[t & 1][idx] = g_gpre[(long)(t - 1) * 131072 + idx];
    }
}

// final LSTM after the loop: h_29 -> H row 28
__global__ void k_lstm_final() {
    int idx = blockIdx.x * 256 + threadIdx.x;
    int b = idx >> 9, d = idx & 511;
    const float* gg = g_gates2[(TT - 1) & 1] + b * 2048;   // t=29 -> parity 1
    const float* cp = g_c2[(TT - 2) & 1] + b * 512;        // (29-1)&1 = 0
    float ig = sigf(gg[d]);
    float fg = sigf(gg[512 + d]);
    float gv = tanhf(gg[1024 + d]);
    float og = sigf(gg[1536 + d]);
    float c2v = fg * cp[d] + ig * gv;
    float h2 = og * tanhf(c2v);
    g_H[((long)(TT - 2) * BATCH + b) * 512 + d] = h2;
}

// attention scores: half2 enc_proj, fp32 math
__global__ void k_att(const float* __restrict__ wf, const float* __restrict__ bf) {
    int b = blockIdx.x / 25;
    int pc = blockIdx.x % 25;
    __shared__ float dp[512], wfs[512];
    dp[threadIdx.x] = g_hgate[b * 1024 + threadIdx.x];
    dp[threadIdx.x + 256] = g_hgate[b * 1024 + threadIdx.x + 256];
    wfs[threadIdx.x] = wf[threadIdx.x];
    wfs[threadIdx.x + 256] = wf[threadIdx.x + 256];
    __syncthreads();
    int p = pc * 8 + (threadIdx.x >> 5);
    int lane = threadIdx.x & 31;
    if (p < PP) {
        const __half2* ep = g_ep2 + ((long)(b * PP + p)) * 256;
        float acc = 0.f;
#pragma unroll
        for (int i = 0; i < 8; i++) {
            int h2i = i * 32 + lane;
            float2 e = __half22float2(ep[h2i]);
            int a = 2 * h2i;
            acc += tanh_a(e.x + dp[a]) * wfs[a];
            acc += tanh_a(e.y + dp[a + 1]) * wfs[a + 1];
        }
#pragma unroll
        for (int off = 16; off; off >>= 1) acc += __shfl_down_sync(0xffffffffu, acc, off);
        if (lane == 0) g_scores[b * PP + p] = acc + bf[0];
    }
}

// softmax + gated ctx; one block per batch, each thread owns one half2 column
__global__ void k_softmax_ctx() {
    int b = blockIdx.x;
    int tid = threadIdx.x;
    __shared__ float sc[256];
    __shared__ float red[256];
    float v = (tid < PP) ? g_scores[b * PP + tid] : -1e30f;
    red[tid] = v;
    __syncthreads();
    for (int s = 128; s > 0; s >>= 1) {
        if (tid < s) red[tid] = fmaxf(red[tid], red[tid + s]);
        __syncthreads();
    }
    float mx = red[0];
    __syncthreads();
    float e = (tid < PP) ? expf(v - mx) : 0.f;
    red[tid] = e;
    __syncthreads();
    for (int s = 128; s > 0; s >>= 1) {
        if (tid < s) red[tid] += red[tid + s];
        __syncthreads();
    }
    sc[tid] = e / red[0];
    __syncthreads();

    const __half2* fp = g_feats2 + (long)b * PP * 256 + tid;
    float ax = 0.f, ay = 0.f;
#pragma unroll 4
    for (int p = 0; p < PP; p++) {
        float2 f = __half22float2(fp[(long)p * 256]);
        float a = sc[p];
        ax += a * f.x;
        ay += a * f.y;
    }
    int d = tid * 2;
    float2 o;
    o.x = ax * g_hgate[b * 1024 + 512 + d];
    o.y = ay * g_hgate[b * 1024 + 512 + d + 1];
    *reinterpret_cast<float2*>(&g_x[b * 1536 + 512 + d]) = o;
}

// ---------------- launcher ----------------
extern "C" void kernel_launch(void* const* d_in, const int* in_sizes, int n_in,
                              void* d_out, int out_size) {
    const float* encoder_feats  = (const float*)d_in[0];
    const float* encoder_pooled = (const float*)d_in[1];
    const int*   captions       = (const int*)d_in[2];
    const float* We_att  = (const float*)d_in[3];
    const float* be_att  = (const float*)d_in[4];
    const float* Wd_att  = (const float*)d_in[5];
    const float* bd_att  = (const float*)d_in[6];
    const float* wf_att  = (const float*)d_in[7];
    const float* bf_att  = (const float*)d_in[8];
    const float* emb_table = (const float*)d_in[9];
    const float* W_ih = (const float*)d_in[10];
    const float* W_hh = (const float*)d_in[11];
    const float* b_ih = (const float*)d_in[12];
    const float* b_hh = (const float*)d_in[13];
    const float* W_init_h = (const float*)d_in[14];
    const float* b_init_h = (const float*)d_in[15];
    const float* W_init_c = (const float*)d_in[16];
    const float* b_init_c = (const float*)d_in[17];
    const float* W_fc  = (const float*)d_in[18];
    const float* b_fc  = (const float*)d_in[19];
    const float* W_beta = (const float*)d_in[20];
    const float* b_beta = (const float*)d_in[21];
    float* out = (float*)d_out;

    void* p;
    cudaGetSymbolAddress(&p, g_x);        float* x_ptr = (float*)p;
    cudaGetSymbolAddress(&p, g_Wcat);     float* wcat_ptr = (float*)p;
    cudaGetSymbolAddress(&p, g_gates2);   float* gates2_ptr = (float*)p;
    cudaGetSymbolAddress(&p, g_bias4);    float* bias4_ptr = (float*)p;
    cudaGetSymbolAddress(&p, g_gpre);     float* gpre_ptr = (float*)p;
    cudaGetSymbolAddress(&p, g_H);        float* H_ptr = (float*)p;
    cudaGetSymbolAddress(&p, g_Aext);     __nv_bfloat16* Aext = (__nv_bfloat16*)p;
    cudaGetSymbolAddress(&p, g_Bext);     __nv_bfloat16* Bext = (__nv_bfloat16*)p;
    cudaGetSymbolAddress(&p, g_Wext);     __nv_bfloat16* Wext = (__nv_bfloat16*)p;
    cudaGetSymbolAddress(&p, g_Wihext);   __nv_bfloat16* Wihext = (__nv_bfloat16*)p;
    cudaGetSymbolAddress(&p, g_Eext);     __nv_bfloat16* Eext = (__nv_bfloat16*)p;

    const int SMEM = 64 * 1024;
    cudaFuncSetAttribute(mma_gemm<0>, cudaFuncAttributeMaxDynamicSharedMemorySize, SMEM);
    cudaFuncSetAttribute(mma_gemm<1>, cudaFuncAttributeMaxDynamicSharedMemorySize, SMEM);
    cudaFuncSetAttribute(mma_gemm<2>, cudaFuncAttributeMaxDynamicSharedMemorySize, SMEM);

    // prologue
    k_zero_t0<<<(BATCH * VV + 255) / 256, 256>>>(out);
    k_init_hc<<<dim3(4, BATCH), 256>>>(encoder_pooled, W_init_h, b_init_h, W_init_c, b_init_c);
    k_wcat<<<(1536 * 2048 + 255) / 256, 256>>>(W_ih, W_hh, b_ih, b_hh);
    k_tsp_ext<<<dim3(940, 16), dim3(32, 8)>>>(W_fc, Bext, VV, NPAD);
    k_tsp_ext<<<dim3(16, 16), dim3(32, 8)>>>(We_att, Wext, 512, 512);
    k_tsp_ext<<<dim3(64, 16), dim3(32, 8)>>>(W_ih, Wihext, 2048, 2048);
    k_cvt_feats<<<(12544 * 512 + 255) / 256, 256>>>(encoder_feats, 12544 * 512);
    k_gather_emb<<<(1856 * 512 + 255) / 256, 256>>>(captions, emb_table);
    mma_gemm<0><<<dim3(4, 98), 256, SMEM>>>(Aext, Wext, nullptr, be_att, 512, 12544, 512);
    mma_gemm<1><<<dim3(16, 15), 256, SMEM>>>(Eext, Wihext, gpre_ptr, bias4_ptr, 2048, 1920, 2048);

    // recurrence: 4 launches per step (LSTM fused into next step's head)
    for (int t = 1; t < TT; t++) {
        k_stepf<<<768, 256>>>(Wd_att, bd_att, W_beta, b_beta, t);
        k_att<<<64 * 25, 256>>>(wf_att, bf_att);
        k_softmax_ctx<<<64, 256>>>();
        gemm_gates<<<dim3(16, 1, 8), 256>>>(x_ptr + 512, wcat_ptr + 512 * 2048,
                                            gates2_ptr + (t & 1) * (BATCH * 2048),
                                            2048, 1536, 128);
    }
    k_lstm_final<<<128, 256>>>();

    // vocab projection (m varies fastest: B L2-resident)
    k_cvt_ext<<<(1920 * 512 + 255) / 256, 256>>>(H_ptr, Aext, 1920 * 512);
    mma_gemm<2><<<dim3(15, NPAD / 128), 256, SMEM>>>(Aext, Bext, out, b_fc,
                                                     VV, (TT - 1) * BATCH, VV);
}